// round 9
// baseline (speedup 1.0000x reference)
#include <cuda_runtime.h>
#include <cuda_fp16.h>
#include <cstdint>

#define B_  16
#define T_  512
#define K_  8
#define NI_ 256
#define UN_ 256
#define G_  1024   // 4*UNITS

// Hoisted x@W + b, GATE-INTERLEAVED: col = 4*u + g  (u=unit 0..255, g=gate).
__device__ float g_xw[(size_t)B_ * T_ * K_ * G_];

__device__ __forceinline__ uint32_t smem_u32(const void* p) {
    uint32_t a;
    asm("{ .reg .u64 t; cvta.to.shared.u64 t, %1; cvt.u32.u64 %0, t; }" : "=r"(a) : "l"(p));
    return a;
}
__device__ __forceinline__ float hsig(float v) {
    return fminf(fmaxf(fmaf(v, 0.2f, 0.5f), 0.0f), 1.0f);
}

#define LDSM4(r0, r1, r2, r3, addr)                                              \
    asm volatile("ldmatrix.sync.aligned.m8n8.x4.shared.b16 {%0,%1,%2,%3}, [%4];" \
                 : "=r"(r0), "=r"(r1), "=r"(r2), "=r"(r3) : "r"(addr))
#define LDSM4T(r0, r1, r2, r3, addr)                                             \
    asm volatile("ldmatrix.sync.aligned.m8n8.x4.trans.shared.b16 {%0,%1,%2,%3}, [%4];" \
                 : "=r"(r0), "=r"(r1), "=r"(r2), "=r"(r3) : "r"(addr))
#define MMA16816(d, a0, a1, a2, a3, b0, b1)                                      \
    asm volatile("mma.sync.aligned.m16n8k16.row.col.f32.f16.f16.f32 "            \
                 "{%0,%1,%2,%3}, {%4,%5,%6,%7}, {%8,%9}, {%0,%1,%2,%3};"         \
                 : "+f"(d[0]), "+f"(d[1]), "+f"(d[2]), "+f"(d[3])                \
                 : "r"(a0), "r"(a1), "r"(a2), "r"(a3), "r"(b0), "r"(b1))

#define MBAR_WAIT(addr, ph) do {                                                          \
    uint32_t _done;                                                                       \
    asm volatile("{ .reg .pred p; mbarrier.try_wait.parity.acquire.cta.shared::cta.b64 "  \
                 "p, [%1], %2; selp.b32 %0,1,0,p; }"                                      \
                 : "=r"(_done) : "r"(addr), "r"(ph) : "memory");                          \
    while (!_done) {                                                                      \
        asm volatile("{ .reg .pred p; mbarrier.try_wait.parity.acquire.cta.shared::cta.b64 " \
                     "p, [%1], %2, 0x989680; selp.b32 %0,1,0,p; }"                        \
                     : "=r"(_done) : "r"(addr), "r"(ph) : "memory");                      \
    }                                                                                     \
} while (0)

#define ST_ASYNC32(raddr, val, rmbar)                                                     \
    asm volatile("st.async.shared::cluster.mbarrier::complete_tx::bytes.b32 [%0], %1, [%2];" \
                 :: "r"(raddr), "r"(val), "r"(rmbar) : "memory")

// ---------------------------------------------------------------------------
// Kernel 1 (HMMA): x@W + b into g_xw, col = 4u+g (unchanged, R8-proven).
// ---------------------------------------------------------------------------
#define AP 264
#define BP 136
#define SM1_A 0
#define SM1_B (128 * AP * 2)
#define SM1_TOT (SM1_B + 256 * BP * 2)

__global__ __launch_bounds__(256, 1) void gemm_xw_hmma(
    const float* __restrict__ x, const float* __restrict__ W,
    const float* __restrict__ bias)
{
    extern __shared__ char smem[];
    const uint32_t sb = smem_u32(smem);
    const int tid = threadIdx.x, w = tid >> 5, l = tid & 31;
    const int nb = blockIdx.x;
    const int bm = blockIdx.y * 128;
    const int k  = blockIdx.z;

    half* As = (half*)(smem + SM1_A);
    for (int idx = tid; idx < 128 * 64; idx += 256) {
        int r = idx >> 6, c4 = idx & 63;
        float4 v = *(const float4*)(x + ((size_t)(bm + r) * K_ + k) * NI_ + c4 * 4);
        __half2 h01 = __floats2half2_rn(v.x, v.y);
        __half2 h23 = __floats2half2_rn(v.z, v.w);
        uint2 pk = make_uint2(*(uint32_t*)&h01, *(uint32_t*)&h23);
        *(uint2*)(As + r * AP + c4 * 4) = pk;
    }
    half* Bs = (half*)(smem + SM1_B);
    for (int idx = tid; idx < 256 * 128; idx += 256) {
        int i = idx >> 7, np = idx & 127;
        int u = np >> 2, g = np & 3;
        Bs[i * BP + np] = __float2half_rn(
            W[((size_t)k * NI_ + i) * G_ + g * 256 + nb * 32 + u]);
    }
    __syncthreads();

    const int wm = w >> 2, wn = w & 3;
    float acc[4][4][4];
#pragma unroll
    for (int a = 0; a < 4; a++)
#pragma unroll
        for (int b = 0; b < 4; b++)
#pragma unroll
            for (int e = 0; e < 4; e++) acc[a][b][e] = 0.0f;

#pragma unroll
    for (int ks = 0; ks < 16; ks++) {
        uint32_t af[4][4], bf[2][4];
#pragma unroll
        for (int ma = 0; ma < 4; ma++) {
            uint32_t aaddr = sb + SM1_A
                + (uint32_t)(wm * 64 + ma * 16 + (l & 15)) * (AP * 2)
                + (uint32_t)ks * 32 + (uint32_t)(l >> 4) * 16;
            LDSM4(af[ma][0], af[ma][1], af[ma][2], af[ma][3], aaddr);
        }
#pragma unroll
        for (int n2 = 0; n2 < 2; n2++) {
            uint32_t baddr = sb + SM1_B
                + (uint32_t)(ks * 16 + ((l >> 3) & 1) * 8 + (l & 7)) * (BP * 2)
                + (uint32_t)(wn * 32 + n2 * 16 + (l >> 4) * 8) * 2;
            LDSM4T(bf[n2][0], bf[n2][1], bf[n2][2], bf[n2][3], baddr);
        }
#pragma unroll
        for (int ma = 0; ma < 4; ma++) {
            MMA16816(acc[ma][0], af[ma][0], af[ma][1], af[ma][2], af[ma][3], bf[0][0], bf[0][1]);
            MMA16816(acc[ma][1], af[ma][0], af[ma][1], af[ma][2], af[ma][3], bf[0][2], bf[0][3]);
            MMA16816(acc[ma][2], af[ma][0], af[ma][1], af[ma][2], af[ma][3], bf[1][0], bf[1][1]);
            MMA16816(acc[ma][3], af[ma][0], af[ma][1], af[ma][2], af[ma][3], bf[1][2], bf[1][3]);
        }
    }

#pragma unroll
    for (int nt = 0; nt < 4; nt++) {
        const int np = wn * 32 + nt * 8 + (l & 3) * 2;
        const int u = np >> 2, g = np & 3;
        const float b0 = __ldg(bias + (size_t)k * G_ + g * 256 + nb * 32 + u);
        const float b1 = __ldg(bias + (size_t)k * G_ + (g + 1) * 256 + nb * 32 + u);
#pragma unroll
        for (int ma = 0; ma < 4; ma++) {
            const int m0 = bm + wm * 64 + ma * 16 + (l >> 2);
            float* p0 = g_xw + ((size_t)m0 * K_ + k) * G_ + nb * 128 + np;
            float* p1 = g_xw + ((size_t)(m0 + 8) * K_ + k) * G_ + nb * 128 + np;
            *(float2*)p0 = make_float2(acc[ma][nt][0] + b0, acc[ma][nt][1] + b1);
            *(float2*)p1 = make_float2(acc[ma][nt][2] + b0, acc[ma][nt][3] + b1);
        }
    }
}

// ---------------------------------------------------------------------------
// Kernel 2: recurrence v5 — transposed MMA with U in registers (R8) +
// direct st.async h-exchange (no staging, no syncthreads, no fence, no bulk)
// + split HMMA accumulation chains.
// ---------------------------------------------------------------------------
#define UTP   264                         // UT scratch pitch (halves)
#define SLAB  2304                        // 16 cells * 144 B
#define HBUF  (4 * SLAB)                  // 9216
#define TXB   8192u                       // 4 CTAs x 2048 B of h per buffer
#define OFF_H   0                         // 2 buffers x 9216
#define OFF_MB  (2 * HBUF)                // 2 mbarriers
#define OFF_UT  (OFF_MB + 128)            // scratch, 256 rows x 528 B
#define SM2_TOT (OFF_UT + 256 * UTP * 2)

__global__ __launch_bounds__(512, 1) __cluster_dims__(4, 1, 1)
void lstm_rec_v5(const float* __restrict__ U, float* __restrict__ out)
{
    extern __shared__ char smem[];
    const uint32_t sb = smem_u32(smem);
    const int tid = threadIdx.x, w = tid >> 5, l = tid & 31;
    const int k = blockIdx.x >> 2;
    uint32_t rank;
    asm("mov.u32 %0, %%cluster_ctarank;" : "=r"(rank));

    // --- Load UT scratch (2 threads per row) ---
    {
        const int j = tid >> 1, hf = tid & 1;
        const int wq = j >> 4, rr = j & 15;
        const int uloc = 4 * wq + (rr & 3), g = rr >> 2;
        const float* up = U + (size_t)k * NI_ * G_ + g * 256 + (int)rank * 64 + uloc;
        half* uts = (half*)(smem + OFF_UT) + (size_t)j * UTP;
        for (int i = hf * 128; i < hf * 128 + 128; i++)
            uts[i] = __float2half_rn(up[(size_t)i * G_]);
    }
    // Zero H buffer 0.
    for (int idx = tid; idx < HBUF / 4; idx += 512)
        ((uint32_t*)(smem + OFF_H))[idx] = 0u;
    if (tid == 0) {
        asm volatile("mbarrier.init.shared.b64 [%0], %1;" :: "r"(sb + OFF_MB), "r"(1u) : "memory");
        asm volatile("mbarrier.init.shared.b64 [%0], %1;" :: "r"(sb + OFF_MB + 8), "r"(1u) : "memory");
        // Pre-arm ONLY buffer-1 barrier (receives end-of-step-0 stores).
        asm volatile("mbarrier.arrive.expect_tx.shared.b64 _, [%0], %1;"
                     :: "r"(sb + OFF_MB + 8), "r"(TXB) : "memory");
    }
    __syncthreads();

    // --- UT -> A-frag registers (once) ---
    uint32_t Af[16][4];
    {
        const uint32_t abase = sb + OFF_UT
            + (uint32_t)(16 * w + (l & 15)) * (UTP * 2) + (uint32_t)(l >> 4) * 16;
#pragma unroll
        for (int ks = 0; ks < 16; ks++)
            LDSM4(Af[ks][0], Af[ks][1], Af[ks][2], Af[ks][3], abase + ks * 32);
    }

    asm volatile("barrier.cluster.arrive.aligned;" ::: "memory");
    asm volatile("barrier.cluster.wait.aligned;" ::: "memory");

    // --- Per-lane constants ---
    const bool lo16 = (l < 16);
    const int  uloc = 4 * w + ((l >> 2) & 3);            // unit (local 0..63)
    const int  cell0 = 2 * (l & 3) + (lo16 ? 0 : 1);     // cells cell0, cell0+8
    const int  colx = 4 * ((int)rank * 64 + uloc);       // xw col base (4u+g)
    const uint32_t hBase = sb + OFF_H + (uint32_t)(l & 15) * 144 + (uint32_t)(l >> 4) * 16;
    const float* xw0p = g_xw + ((size_t)cell0 * T_ * K_ + k) * G_ + colx;
    const float* xw1p = g_xw + ((size_t)(cell0 + 8) * T_ * K_ + k) * G_ + colx;
    const bool sender = ((l >> 2) & 1) == 0;             // even unit of shfl-4 pair
    float c0 = 0.0f, c1 = 0.0f;
    int ph0 = 0, ph1 = 0;

    for (int t = 0; t < T_; t++) {
        const int p = t & 1;

        // xw prefetch: all 4 gates of (unit, cell) as float4.
        float4 xwa = __ldg((const float4*)(xw0p + (size_t)t * (K_ * G_)));
        float4 xwb = __ldg((const float4*)(xw1p + (size_t)t * (K_ * G_)));

        if (t > 0) {
            if (p) { MBAR_WAIT(sb + OFF_MB + 8, (uint32_t)ph1); ph1 ^= 1; }
            else   { MBAR_WAIT(sb + OFF_MB,     (uint32_t)ph0); ph0 ^= 1; }
        }
        if (tid == 0)
            asm volatile("mbarrier.arrive.expect_tx.shared.b64 _, [%0], %1;"
                         :: "r"(sb + OFF_MB + (uint32_t)p * 8), "r"(TXB) : "memory");

        // MMA: Z^T[16 zcols, 16 cells] over K=256, 4 independent chains.
        float dA0[4] = {0, 0, 0, 0}, dB0[4] = {0, 0, 0, 0};
        float dA1[4] = {0, 0, 0, 0}, dB1[4] = {0, 0, 0, 0};
        const uint32_t hA = hBase + (uint32_t)p * HBUF;
#pragma unroll
        for (int ks = 0; ks < 8; ks++) {
            uint32_t t0, t1, t2, t3;
            LDSM4(t0, t1, t2, t3, hA + (uint32_t)(ks >> 2) * SLAB + (uint32_t)(ks & 3) * 32);
            MMA16816(dA0, Af[ks][0], Af[ks][1], Af[ks][2], Af[ks][3], t0, t2);
            MMA16816(dA1, Af[ks][0], Af[ks][1], Af[ks][2], Af[ks][3], t1, t3);
        }
#pragma unroll
        for (int ks = 8; ks < 16; ks++) {
            uint32_t t0, t1, t2, t3;
            LDSM4(t0, t1, t2, t3, hA + (uint32_t)(ks >> 2) * SLAB + (uint32_t)(ks & 3) * 32);
            MMA16816(dB0, Af[ks][0], Af[ks][1], Af[ks][2], Af[ks][3], t0, t2);
            MMA16816(dB1, Af[ks][0], Af[ks][1], Af[ks][2], Af[ks][3], t1, t3);
        }
        float dLo[4], dHi[4];
#pragma unroll
        for (int e = 0; e < 4; e++) { dLo[e] = dA0[e] + dB0[e]; dHi[e] = dA1[e] + dB1[e]; }

        // Redistribute gates across lane-pair (l, l^16).
        float xa = __shfl_xor_sync(0xFFFFFFFFu, lo16 ? dLo[1] : dLo[0], 16);
        float xb = __shfl_xor_sync(0xFFFFFFFFu, lo16 ? dLo[3] : dLo[2], 16);
        float xc = __shfl_xor_sync(0xFFFFFFFFu, lo16 ? dHi[1] : dHi[0], 16);
        float xd = __shfl_xor_sync(0xFFFFFFFFu, lo16 ? dHi[3] : dHi[2], 16);

        float zA0, zA1, zA2, zA3, zB0, zB1, zB2, zB3;
        if (lo16) { zA0 = dLo[0]; zA1 = xa;     zA2 = dLo[2]; zA3 = xb;
                    zB0 = dHi[0]; zB1 = xc;     zB2 = dHi[2]; zB3 = xd; }
        else      { zA0 = xa;     zA1 = dLo[1]; zA2 = xb;     zA3 = dLo[3];
                    zB0 = xc;     zB1 = dHi[1]; zB2 = xd;     zB3 = dHi[3]; }

        // Epilogue: 2 full (unit, cell) updates in registers.
        float av0 = tanhf(zA0 + xwa.x);
        float iv0 = hsig (zA1 + xwa.y);
        float fv0 = hsig (zA2 + xwa.z);
        float ov0 = hsig (zA3 + xwa.w);
        c0 = fmaf(fv0, c0, av0 * iv0);
        float h0 = ov0 * tanhf(c0);

        float av1 = tanhf(zB0 + xwb.x);
        float iv1 = hsig (zB1 + xwb.y);
        float fv1 = hsig (zB2 + xwb.z);
        float ov1 = hsig (zB3 + xwb.w);
        c1 = fmaf(fv1, c1, av1 * iv1);
        float h1 = ov1 * tanhf(c1);

        // Direct DSMEM exchange: pack unit pair (shfl xor 4), even lane of
        // pair stores both cells' b32 into all 4 CTAs' H buffers with
        // store-carried tx completion.
        float q0 = __shfl_xor_sync(0xFFFFFFFFu, h0, 4);
        float q1 = __shfl_xor_sync(0xFFFFFFFFu, h1, 4);
        if (sender) {
            __half2 v0h = __floats2half2_rn(h0, q0);
            __half2 v1h = __floats2half2_rn(h1, q1);
            const uint32_t v0 = *(const uint32_t*)&v0h;
            const uint32_t v1 = *(const uint32_t*)&v1h;
            const uint32_t a0L = sb + OFF_H + (uint32_t)(p ^ 1) * HBUF + rank * SLAB
                               + (uint32_t)cell0 * 144 + (uint32_t)uloc * 2;
            const uint32_t mbL = sb + OFF_MB + (uint32_t)(p ^ 1) * 8;
#pragma unroll
            for (int peer = 0; peer < 4; peer++) {
                uint32_t ra, rm;
                asm("mapa.shared::cluster.u32 %0, %1, %2;" : "=r"(ra) : "r"(a0L), "r"(peer));
                asm("mapa.shared::cluster.u32 %0, %1, %2;" : "=r"(rm) : "r"(mbL), "r"(peer));
                ST_ASYNC32(ra, v0, rm);
                ST_ASYNC32(ra + 8u * 144u, v1, rm);
            }
        }

        // Global out stores (after remote h is in flight).
        out[(((size_t)cell0 * T_ + t) * K_ + k) * UN_ + (size_t)rank * 64 + uloc] = h0;
        out[(((size_t)(cell0 + 8) * T_ + t) * K_ + k) * UN_ + (size_t)rank * 64 + uloc] = h1;
    }

    // Keep smem alive until all peers' last stores land.
    asm volatile("barrier.cluster.arrive.aligned;" ::: "memory");
    asm volatile("barrier.cluster.wait.aligned;" ::: "memory");
}

// ---------------------------------------------------------------------------
extern "C" void kernel_launch(void* const* d_in, const int* in_sizes, int n_in,
                              void* d_out, int out_size)
{
    const float* x = (const float*)d_in[0];
    const float* W = (const float*)d_in[1];
    const float* U = (const float*)d_in[2];
    const float* b = (const float*)d_in[3];
    float* out = (float*)d_out;

    cudaFuncSetAttribute(gemm_xw_hmma, cudaFuncAttributeMaxDynamicSharedMemorySize, SM1_TOT);
    dim3 g1(8, 64, 8);
    gemm_xw_hmma<<<g1, 256, SM1_TOT>>>(x, W, b);

    cudaFuncSetAttribute(lstm_rec_v5, cudaFuncAttributeMaxDynamicSharedMemorySize, SM2_TOT);
    lstm_rec_v5<<<K_ * 4, 512, SM2_TOT>>>(U, out);
}

// round 10
// speedup vs baseline: 1.0606x; 1.0606x over previous
#include <cuda_runtime.h>
#include <cuda_fp16.h>
#include <cstdint>

#define B_  16
#define T_  512
#define K_  8
#define NI_ 256
#define UN_ 256
#define G_  1024   // 4*UNITS

// Hoisted x@W + b, GATE-INTERLEAVED: col = 4*u + g  (u=unit 0..255, g=gate).
__device__ float g_xw[(size_t)B_ * T_ * K_ * G_];

__device__ __forceinline__ uint32_t smem_u32(const void* p) {
    uint32_t a;
    asm("{ .reg .u64 t; cvta.to.shared.u64 t, %1; cvt.u32.u64 %0, t; }" : "=r"(a) : "l"(p));
    return a;
}
__device__ __forceinline__ float hsig(float v) {
    return fminf(fmaxf(fmaf(v, 0.2f, 0.5f), 0.0f), 1.0f);
}

#define LDSM4(r0, r1, r2, r3, addr)                                              \
    asm volatile("ldmatrix.sync.aligned.m8n8.x4.shared.b16 {%0,%1,%2,%3}, [%4];" \
                 : "=r"(r0), "=r"(r1), "=r"(r2), "=r"(r3) : "r"(addr))
#define LDSM2(r0, r1, addr)                                                      \
    asm volatile("ldmatrix.sync.aligned.m8n8.x2.shared.b16 {%0,%1}, [%2];"       \
                 : "=r"(r0), "=r"(r1) : "r"(addr))
#define LDSM4T(r0, r1, r2, r3, addr)                                             \
    asm volatile("ldmatrix.sync.aligned.m8n8.x4.trans.shared.b16 {%0,%1,%2,%3}, [%4];" \
                 : "=r"(r0), "=r"(r1), "=r"(r2), "=r"(r3) : "r"(addr))
#define MMA16816(d, a0, a1, a2, a3, b0, b1)                                      \
    asm volatile("mma.sync.aligned.m16n8k16.row.col.f32.f16.f16.f32 "            \
                 "{%0,%1,%2,%3}, {%4,%5,%6,%7}, {%8,%9}, {%0,%1,%2,%3};"         \
                 : "+f"(d[0]), "+f"(d[1]), "+f"(d[2]), "+f"(d[3])                \
                 : "r"(a0), "r"(a1), "r"(a2), "r"(a3), "r"(b0), "r"(b1))

#define MBAR_WAIT(addr, ph) do {                                                          \
    uint32_t _done;                                                                       \
    asm volatile("{ .reg .pred p; mbarrier.try_wait.parity.acquire.cta.shared::cta.b64 "  \
                 "p, [%1], %2; selp.b32 %0,1,0,p; }"                                      \
                 : "=r"(_done) : "r"(addr), "r"(ph) : "memory");                          \
    while (!_done) {                                                                      \
        asm volatile("{ .reg .pred p; mbarrier.try_wait.parity.acquire.cta.shared::cta.b64 " \
                     "p, [%1], %2, 0x989680; selp.b32 %0,1,0,p; }"                        \
                     : "=r"(_done) : "r"(addr), "r"(ph) : "memory");                      \
    }                                                                                     \
} while (0)

// ---------------------------------------------------------------------------
// Kernel 1 (HMMA): x@W + b into g_xw, col = 4u+g (unchanged, R8-proven).
// ---------------------------------------------------------------------------
#define AP 264
#define BP 136
#define SM1_A 0
#define SM1_B (128 * AP * 2)
#define SM1_TOT (SM1_B + 256 * BP * 2)

__global__ __launch_bounds__(256, 1) void gemm_xw_hmma(
    const float* __restrict__ x, const float* __restrict__ W,
    const float* __restrict__ bias)
{
    extern __shared__ char smem[];
    const uint32_t sb = smem_u32(smem);
    const int tid = threadIdx.x, w = tid >> 5, l = tid & 31;
    const int nb = blockIdx.x;
    const int bm = blockIdx.y * 128;
    const int k  = blockIdx.z;

    half* As = (half*)(smem + SM1_A);
    for (int idx = tid; idx < 128 * 64; idx += 256) {
        int r = idx >> 6, c4 = idx & 63;
        float4 v = *(const float4*)(x + ((size_t)(bm + r) * K_ + k) * NI_ + c4 * 4);
        __half2 h01 = __floats2half2_rn(v.x, v.y);
        __half2 h23 = __floats2half2_rn(v.z, v.w);
        uint2 pk = make_uint2(*(uint32_t*)&h01, *(uint32_t*)&h23);
        *(uint2*)(As + r * AP + c4 * 4) = pk;
    }
    half* Bs = (half*)(smem + SM1_B);
    for (int idx = tid; idx < 256 * 128; idx += 256) {
        int i = idx >> 7, np = idx & 127;
        int u = np >> 2, g = np & 3;
        Bs[i * BP + np] = __float2half_rn(
            W[((size_t)k * NI_ + i) * G_ + g * 256 + nb * 32 + u]);
    }
    __syncthreads();

    const int wm = w >> 2, wn = w & 3;
    float acc[4][4][4];
#pragma unroll
    for (int a = 0; a < 4; a++)
#pragma unroll
        for (int b = 0; b < 4; b++)
#pragma unroll
            for (int e = 0; e < 4; e++) acc[a][b][e] = 0.0f;

#pragma unroll
    for (int ks = 0; ks < 16; ks++) {
        uint32_t af[4][4], bf[2][4];
#pragma unroll
        for (int ma = 0; ma < 4; ma++) {
            uint32_t aaddr = sb + SM1_A
                + (uint32_t)(wm * 64 + ma * 16 + (l & 15)) * (AP * 2)
                + (uint32_t)ks * 32 + (uint32_t)(l >> 4) * 16;
            LDSM4(af[ma][0], af[ma][1], af[ma][2], af[ma][3], aaddr);
        }
#pragma unroll
        for (int n2 = 0; n2 < 2; n2++) {
            uint32_t baddr = sb + SM1_B
                + (uint32_t)(ks * 16 + ((l >> 3) & 1) * 8 + (l & 7)) * (BP * 2)
                + (uint32_t)(wn * 32 + n2 * 16 + (l >> 4) * 8) * 2;
            LDSM4T(bf[n2][0], bf[n2][1], bf[n2][2], bf[n2][3], baddr);
        }
#pragma unroll
        for (int ma = 0; ma < 4; ma++) {
            MMA16816(acc[ma][0], af[ma][0], af[ma][1], af[ma][2], af[ma][3], bf[0][0], bf[0][1]);
            MMA16816(acc[ma][1], af[ma][0], af[ma][1], af[ma][2], af[ma][3], bf[0][2], bf[0][3]);
            MMA16816(acc[ma][2], af[ma][0], af[ma][1], af[ma][2], af[ma][3], bf[1][0], bf[1][1]);
            MMA16816(acc[ma][3], af[ma][0], af[ma][1], af[ma][2], af[ma][3], bf[1][2], bf[1][3]);
        }
    }

#pragma unroll
    for (int nt = 0; nt < 4; nt++) {
        const int np = wn * 32 + nt * 8 + (l & 3) * 2;
        const int u = np >> 2, g = np & 3;
        const float b0 = __ldg(bias + (size_t)k * G_ + g * 256 + nb * 32 + u);
        const float b1 = __ldg(bias + (size_t)k * G_ + (g + 1) * 256 + nb * 32 + u);
#pragma unroll
        for (int ma = 0; ma < 4; ma++) {
            const int m0 = bm + wm * 64 + ma * 16 + (l >> 2);
            float* p0 = g_xw + ((size_t)m0 * K_ + k) * G_ + nb * 128 + np;
            float* p1 = g_xw + ((size_t)(m0 + 8) * K_ + k) * G_ + nb * 128 + np;
            *(float2*)p0 = make_float2(acc[ma][nt][0] + b0, acc[ma][nt][1] + b1);
            *(float2*)p1 = make_float2(acc[ma][nt][2] + b0, acc[ma][nt][3] + b1);
        }
    }
}

// ---------------------------------------------------------------------------
// Kernel 2: recurrence v6 — two-phase cell-split pipeline.
// Phase A = cells 0-7, phase B = cells 8-15, each with own mbarrier pair;
// half-A exchange (3 remote bulks, self written directly) overlaps half-B
// compute. U in registers (R8), bulk DSMEM ring (R8), split MMA chains (R9).
// ---------------------------------------------------------------------------
#define UTP   264                         // UT scratch pitch (halves)
#define SLAB  2304                        // 16 cells * 144 B
#define HALFB 1152                        // 8 cells * 144 B
#define HBUF  (4 * SLAB)                  // 9216
#define TXH   (3u * HALFB)                // 3 remote CTAs per half
#define OFF_H   0                         // 2 buffers x 9216
#define OFF_STG (2 * HBUF)                // 2 parities x 2304
#define OFF_MB  (OFF_STG + 2 * SLAB)      // 4 mbarriers: [buf][half]
#define OFF_UT  (OFF_MB + 128)            // scratch, 256 rows x 528 B
#define SM2_TOT (OFF_UT + 256 * UTP * 2)

__global__ __launch_bounds__(512, 1) __cluster_dims__(4, 1, 1)
void lstm_rec_v6(const float* __restrict__ U, float* __restrict__ out)
{
    extern __shared__ char smem[];
    const uint32_t sb = smem_u32(smem);
    const int tid = threadIdx.x, w = tid >> 5, l = tid & 31;
    const int k = blockIdx.x >> 2;
    uint32_t rank;
    asm("mov.u32 %0, %%cluster_ctarank;" : "=r"(rank));

    // --- Load UT scratch (2 threads per row) ---
    {
        const int j = tid >> 1, hf = tid & 1;
        const int wq = j >> 4, rr = j & 15;
        const int uloc = 4 * wq + (rr & 3), g = rr >> 2;
        const float* up = U + (size_t)k * NI_ * G_ + g * 256 + (int)rank * 64 + uloc;
        half* uts = (half*)(smem + OFF_UT) + (size_t)j * UTP;
        for (int i = hf * 128; i < hf * 128 + 128; i++)
            uts[i] = __float2half_rn(up[(size_t)i * G_]);
    }
    // Zero H buffer 0.
    for (int idx = tid; idx < HBUF / 4; idx += 512)
        ((uint32_t*)(smem + OFF_H))[idx] = 0u;
    if (tid == 0) {
#pragma unroll
        for (int b = 0; b < 4; b++)
            asm volatile("mbarrier.init.shared.b64 [%0], %1;"
                         :: "r"(sb + OFF_MB + b * 8), "r"(1u) : "memory");
        // Pre-arm ONLY buffer-1 barriers (receive step-0 copies).
        asm volatile("mbarrier.arrive.expect_tx.shared.b64 _, [%0], %1;"
                     :: "r"(sb + OFF_MB + 16), "r"(TXH) : "memory");
        asm volatile("mbarrier.arrive.expect_tx.shared.b64 _, [%0], %1;"
                     :: "r"(sb + OFF_MB + 24), "r"(TXH) : "memory");
    }
    __syncthreads();

    // --- UT -> A-frag registers (once) ---
    uint32_t Af[16][4];
    {
        const uint32_t abase = sb + OFF_UT
            + (uint32_t)(16 * w + (l & 15)) * (UTP * 2) + (uint32_t)(l >> 4) * 16;
#pragma unroll
        for (int ks = 0; ks < 16; ks++)
            LDSM4(Af[ks][0], Af[ks][1], Af[ks][2], Af[ks][3], abase + ks * 32);
    }

    asm volatile("barrier.cluster.arrive.aligned;" ::: "memory");
    asm volatile("barrier.cluster.wait.aligned;" ::: "memory");

    // --- Per-lane constants ---
    const bool lo16 = (l < 16);
    const int  uloc = 4 * w + ((l >> 2) & 3);          // unit (local 0..63)
    const int  cell0 = 2 * (l & 3) + (lo16 ? 0 : 1);   // phase-A cell; B = +8
    const int  colx = 4 * ((int)rank * 64 + uloc);     // xw col base (4u+g)
    // ldmatrix.x2 source (lanes 0-15 meaningful): row (l&7), 16B half (l>>3)&1
    const uint32_t aHalf = sb + OFF_H + (uint32_t)(l & 7) * 144 + (uint32_t)((l >> 3) & 1) * 16;
    const float* xw0p = g_xw + ((size_t)cell0 * T_ * K_ + k) * G_ + colx;
    const float* xw1p = g_xw + ((size_t)(cell0 + 8) * T_ * K_ + k) * G_ + colx;
    const bool sender = ((l >> 2) & 1) == 0;
    float c0 = 0.0f, c1 = 0.0f;
    int phA0 = 0, phA1 = 0, phB0 = 0, phB1 = 0;

    for (int t = 0; t < T_; t++) {
        const int p = t & 1;
        const uint32_t mbA = sb + OFF_MB + (uint32_t)p * 16;        // [p][A]
        const uint32_t mbB = mbA + 8;                               // [p][B]

        // xw prefetch for both phases.
        float4 xwa = __ldg((const float4*)(xw0p + (size_t)t * (K_ * G_)));
        float4 xwb = __ldg((const float4*)(xw1p + (size_t)t * (K_ * G_)));

        // ================= PHASE A : cells 0-7 =================
        if (t > 0) {
            if (p) { MBAR_WAIT(mbA, (uint32_t)phA1); phA1 ^= 1; }
            else   { MBAR_WAIT(mbA, (uint32_t)phA0); phA0 ^= 1; }
        }
        if (tid == 0)
            asm volatile("mbarrier.arrive.expect_tx.shared.b64 _, [%0], %1;"
                         :: "r"(mbA), "r"(TXH) : "memory");

        float dP[4] = {0, 0, 0, 0}, dQ[4] = {0, 0, 0, 0};
        {
            const uint32_t hA = aHalf + (uint32_t)p * HBUF;
#pragma unroll
            for (int ks = 0; ks < 8; ks++) {
                uint32_t b0, b1;
                LDSM2(b0, b1, hA + (uint32_t)(ks >> 2) * SLAB + (uint32_t)(ks & 3) * 32);
                MMA16816(dP, Af[ks][0], Af[ks][1], Af[ks][2], Af[ks][3], b0, b1);
            }
#pragma unroll
            for (int ks = 8; ks < 16; ks++) {
                uint32_t b0, b1;
                LDSM2(b0, b1, hA + (uint32_t)(ks >> 2) * SLAB + (uint32_t)(ks & 3) * 32);
                MMA16816(dQ, Af[ks][0], Af[ks][1], Af[ks][2], Af[ks][3], b0, b1);
            }
        }
        float dLo[4];
#pragma unroll
        for (int e = 0; e < 4; e++) dLo[e] = dP[e] + dQ[e];

        float xa = __shfl_xor_sync(0xFFFFFFFFu, lo16 ? dLo[1] : dLo[0], 16);
        float xb = __shfl_xor_sync(0xFFFFFFFFu, lo16 ? dLo[3] : dLo[2], 16);
        float zA0, zA1, zA2, zA3;
        if (lo16) { zA0 = dLo[0]; zA1 = xa;     zA2 = dLo[2]; zA3 = xb;     }
        else      { zA0 = xa;     zA1 = dLo[1]; zA2 = xb;     zA3 = dLo[3]; }

        float av0 = tanhf(zA0 + xwa.x);
        float iv0 = hsig (zA1 + xwa.y);
        float fv0 = hsig (zA2 + xwa.z);
        float ov0 = hsig (zA3 + xwa.w);
        c0 = fmaf(fv0, c0, av0 * iv0);
        float h0 = ov0 * tanhf(c0);

        float q0 = __shfl_xor_sync(0xFFFFFFFFu, h0, 4);
        if (sender) {
            __half2 v = __floats2half2_rn(h0, q0);
            const uint32_t off = (uint32_t)cell0 * 144 + (uint32_t)uloc * 2;
            *(__half2*)(smem + OFF_STG + p * SLAB + off) = v;                        // staging
            *(__half2*)(smem + OFF_H + (p ^ 1) * HBUF + rank * SLAB + off) = v;      // local slab
        }
        out[(((size_t)cell0 * T_ + t) * K_ + k) * UN_ + (size_t)rank * 64 + uloc] = h0;

        __syncthreads();
        if (tid == 0) {
            asm volatile("fence.proxy.async;" ::: "memory");
            const uint32_t src  = sb + OFF_STG + (uint32_t)p * SLAB;                 // half A
            const uint32_t dstL = sb + OFF_H + (uint32_t)(p ^ 1) * HBUF + rank * SLAB;
            const uint32_t mbL  = sb + OFF_MB + (uint32_t)(p ^ 1) * 16;              // [p^1][A]
#pragma unroll
            for (int peer = 0; peer < 4; peer++) {
                if (peer == (int)rank) continue;
                uint32_t dstR, mbR;
                asm("mapa.shared::cluster.u32 %0, %1, %2;" : "=r"(dstR) : "r"(dstL), "r"(peer));
                asm("mapa.shared::cluster.u32 %0, %1, %2;" : "=r"(mbR)  : "r"(mbL),  "r"(peer));
                asm volatile(
                    "cp.async.bulk.shared::cluster.shared::cta.mbarrier::complete_tx::bytes "
                    "[%0], [%1], %2, [%3];"
                    :: "r"(dstR), "r"(src), "r"((uint32_t)HALFB), "r"(mbR) : "memory");
            }
        }

        // ================= PHASE B : cells 8-15 =================
        if (t > 0) {
            if (p) { MBAR_WAIT(mbB, (uint32_t)phB1); phB1 ^= 1; }
            else   { MBAR_WAIT(mbB, (uint32_t)phB0); phB0 ^= 1; }
        }
        if (tid == 0)
            asm volatile("mbarrier.arrive.expect_tx.shared.b64 _, [%0], %1;"
                         :: "r"(mbB), "r"(TXH) : "memory");

        float eP[4] = {0, 0, 0, 0}, eQ[4] = {0, 0, 0, 0};
        {
            const uint32_t hB = aHalf + (uint32_t)p * HBUF + 8u * 144u;
#pragma unroll
            for (int ks = 0; ks < 8; ks++) {
                uint32_t b0, b1;
                LDSM2(b0, b1, hB + (uint32_t)(ks >> 2) * SLAB + (uint32_t)(ks & 3) * 32);
                MMA16816(eP, Af[ks][0], Af[ks][1], Af[ks][2], Af[ks][3], b0, b1);
            }
#pragma unroll
            for (int ks = 8; ks < 16; ks++) {
                uint32_t b0, b1;
                LDSM2(b0, b1, hB + (uint32_t)(ks >> 2) * SLAB + (uint32_t)(ks & 3) * 32);
                MMA16816(eQ, Af[ks][0], Af[ks][1], Af[ks][2], Af[ks][3], b0, b1);
            }
        }
        float dHi[4];
#pragma unroll
        for (int e = 0; e < 4; e++) dHi[e] = eP[e] + eQ[e];

        float xc = __shfl_xor_sync(0xFFFFFFFFu, lo16 ? dHi[1] : dHi[0], 16);
        float xd = __shfl_xor_sync(0xFFFFFFFFu, lo16 ? dHi[3] : dHi[2], 16);
        float zB0, zB1, zB2, zB3;
        if (lo16) { zB0 = dHi[0]; zB1 = xc;     zB2 = dHi[2]; zB3 = xd;     }
        else      { zB0 = xc;     zB1 = dHi[1]; zB2 = xd;     zB3 = dHi[3]; }

        float av1 = tanhf(zB0 + xwb.x);
        float iv1 = hsig (zB1 + xwb.y);
        float fv1 = hsig (zB2 + xwb.z);
        float ov1 = hsig (zB3 + xwb.w);
        c1 = fmaf(fv1, c1, av1 * iv1);
        float h1 = ov1 * tanhf(c1);

        float q1 = __shfl_xor_sync(0xFFFFFFFFu, h1, 4);
        if (sender) {
            __half2 v = __floats2half2_rn(h1, q1);
            const uint32_t off = (uint32_t)(cell0 + 8) * 144 + (uint32_t)uloc * 2;
            *(__half2*)(smem + OFF_STG + p * SLAB + off) = v;
            *(__half2*)(smem + OFF_H + (p ^ 1) * HBUF + rank * SLAB + off) = v;
        }
        out[(((size_t)(cell0 + 8) * T_ + t) * K_ + k) * UN_ + (size_t)rank * 64 + uloc] = h1;

        __syncthreads();
        if (tid == 0) {
            asm volatile("fence.proxy.async;" ::: "memory");
            const uint32_t src  = sb + OFF_STG + (uint32_t)p * SLAB + HALFB;         // half B
            const uint32_t dstL = sb + OFF_H + (uint32_t)(p ^ 1) * HBUF + rank * SLAB + HALFB;
            const uint32_t mbL  = sb + OFF_MB + (uint32_t)(p ^ 1) * 16 + 8;          // [p^1][B]
#pragma unroll
            for (int peer = 0; peer < 4; peer++) {
                if (peer == (int)rank) continue;
                uint32_t dstR, mbR;
                asm("mapa.shared::cluster.u32 %0, %1, %2;" : "=r"(dstR) : "r"(dstL), "r"(peer));
                asm("mapa.shared::cluster.u32 %0, %1, %2;" : "=r"(mbR)  : "r"(mbL),  "r"(peer));
                asm volatile(
                    "cp.async.bulk.shared::cluster.shared::cta.mbarrier::complete_tx::bytes "
                    "[%0], [%1], %2, [%3];"
                    :: "r"(dstR), "r"(src), "r"((uint32_t)HALFB), "r"(mbR) : "memory");
            }
        }
    }

    // Keep smem alive until all peers' last copies land.
    asm volatile("barrier.cluster.arrive.aligned;" ::: "memory");
    asm volatile("barrier.cluster.wait.aligned;" ::: "memory");
}

// ---------------------------------------------------------------------------
extern "C" void kernel_launch(void* const* d_in, const int* in_sizes, int n_in,
                              void* d_out, int out_size)
{
    const float* x = (const float*)d_in[0];
    const float* W = (const float*)d_in[1];
    const float* U = (const float*)d_in[2];
    const float* b = (const float*)d_in[3];
    float* out = (float*)d_out;

    cudaFuncSetAttribute(gemm_xw_hmma, cudaFuncAttributeMaxDynamicSharedMemorySize, SM1_TOT);
    dim3 g1(8, 64, 8);
    gemm_xw_hmma<<<g1, 256, SM1_TOT>>>(x, W, b);

    cudaFuncSetAttribute(lstm_rec_v6, cudaFuncAttributeMaxDynamicSharedMemorySize, SM2_TOT);
    lstm_rec_v6<<<K_ * 4, 512, SM2_TOT>>>(U, out);
}

// round 12
// speedup vs baseline: 1.3025x; 1.2281x over previous
#include <cuda_runtime.h>
#include <cuda_fp16.h>
#include <cstdint>

#define B_  16
#define T_  512
#define K_  8
#define NI_ 256
#define UN_ 256
#define G_  1024   // 4*UNITS

// Hoisted x@W + b, GATE-INTERLEAVED: col = 4*u + g  (u=unit 0..255, g=gate).
__device__ float g_xw[(size_t)B_ * T_ * K_ * G_];
// Progress flags: g_flags[k][chunk] counts completed GEMM blocks (target 128).
__device__ unsigned int g_flags[K_][4];

__device__ __forceinline__ uint32_t smem_u32(const void* p) {
    uint32_t a;
    asm("{ .reg .u64 t; cvta.to.shared.u64 t, %1; cvt.u32.u64 %0, t; }" : "=r"(a) : "l"(p));
    return a;
}
__device__ __forceinline__ float hsig(float v) {
    return fminf(fmaxf(fmaf(v, 0.2f, 0.5f), 0.0f), 1.0f);
}

#define LDSM4(r0, r1, r2, r3, addr)                                              \
    asm volatile("ldmatrix.sync.aligned.m8n8.x4.shared.b16 {%0,%1,%2,%3}, [%4];" \
                 : "=r"(r0), "=r"(r1), "=r"(r2), "=r"(r3) : "r"(addr))
#define LDSM2(r0, r1, addr)                                                      \
    asm volatile("ldmatrix.sync.aligned.m8n8.x2.shared.b16 {%0,%1}, [%2];"       \
                 : "=r"(r0), "=r"(r1) : "r"(addr))
#define LDSM4T(r0, r1, r2, r3, addr)                                             \
    asm volatile("ldmatrix.sync.aligned.m8n8.x4.trans.shared.b16 {%0,%1,%2,%3}, [%4];" \
                 : "=r"(r0), "=r"(r1), "=r"(r2), "=r"(r3) : "r"(addr))
#define MMA16816(d, a0, a1, a2, a3, b0, b1)                                      \
    asm volatile("mma.sync.aligned.m16n8k16.row.col.f32.f16.f16.f32 "            \
                 "{%0,%1,%2,%3}, {%4,%5,%6,%7}, {%8,%9}, {%0,%1,%2,%3};"         \
                 : "+f"(d[0]), "+f"(d[1]), "+f"(d[2]), "+f"(d[3])                \
                 : "r"(a0), "r"(a1), "r"(a2), "r"(a3), "r"(b0), "r"(b1))

#define MBAR_WAIT(addr, ph) do {                                                          \
    uint32_t _done;                                                                       \
    asm volatile("{ .reg .pred p; mbarrier.try_wait.parity.acquire.cta.shared::cta.b64 "  \
                 "p, [%1], %2; selp.b32 %0,1,0,p; }"                                      \
                 : "=r"(_done) : "r"(addr), "r"(ph) : "memory");                          \
    while (!_done) {                                                                      \
        asm volatile("{ .reg .pred p; mbarrier.try_wait.parity.acquire.cta.shared::cta.b64 " \
                     "p, [%1], %2, 0x989680; selp.b32 %0,1,0,p; }"                        \
                     : "=r"(_done) : "r"(addr), "r"(ph) : "memory");                      \
    }                                                                                     \
} while (0)

// ---------------------------------------------------------------------------
// Kernel 1 (HMMA): x@W + b into g_xw, col = 4u+g. Chunk-major grid + release
// completion flags for producer/consumer overlap.
// ---------------------------------------------------------------------------
#define AP 264
#define BP 136
#define SM1_A 0
#define SM1_B (128 * AP * 2)
#define SM1_TOT (SM1_B + 256 * BP * 2)

__global__ __launch_bounds__(256, 1) void gemm_xw_hmma(
    const float* __restrict__ x, const float* __restrict__ W,
    const float* __restrict__ bias)
{
    extern __shared__ char smem[];
    const uint32_t sb = smem_u32(smem);
    const int tid = threadIdx.x, w = tid >> 5, l = tid & 31;
    const int nb    = blockIdx.x;            // 32-unit block
    const int k     = blockIdx.y >> 4;
    const int cell  = blockIdx.y & 15;
    const int chunk = blockIdx.z;            // t-chunk (slowest: scheduled first)
    const int bm    = (cell * 4 + chunk) * 128;

    half* As = (half*)(smem + SM1_A);
    for (int idx = tid; idx < 128 * 64; idx += 256) {
        int r = idx >> 6, c4 = idx & 63;
        float4 v = *(const float4*)(x + ((size_t)(bm + r) * K_ + k) * NI_ + c4 * 4);
        __half2 h01 = __floats2half2_rn(v.x, v.y);
        __half2 h23 = __floats2half2_rn(v.z, v.w);
        uint2 pk = make_uint2(*(uint32_t*)&h01, *(uint32_t*)&h23);
        *(uint2*)(As + r * AP + c4 * 4) = pk;
    }
    half* Bs = (half*)(smem + SM1_B);
    for (int idx = tid; idx < 256 * 128; idx += 256) {
        int i = idx >> 7, np = idx & 127;
        int u = np >> 2, g = np & 3;
        Bs[i * BP + np] = __float2half_rn(
            W[((size_t)k * NI_ + i) * G_ + g * 256 + nb * 32 + u]);
    }
    __syncthreads();

    const int wm = w >> 2, wn = w & 3;
    float acc[4][4][4];
#pragma unroll
    for (int a = 0; a < 4; a++)
#pragma unroll
        for (int b = 0; b < 4; b++)
#pragma unroll
            for (int e = 0; e < 4; e++) acc[a][b][e] = 0.0f;

#pragma unroll
    for (int ks = 0; ks < 16; ks++) {
        uint32_t af[4][4], bf[2][4];
#pragma unroll
        for (int ma = 0; ma < 4; ma++) {
            uint32_t aaddr = sb + SM1_A
                + (uint32_t)(wm * 64 + ma * 16 + (l & 15)) * (AP * 2)
                + (uint32_t)ks * 32 + (uint32_t)(l >> 4) * 16;
            LDSM4(af[ma][0], af[ma][1], af[ma][2], af[ma][3], aaddr);
        }
#pragma unroll
        for (int n2 = 0; n2 < 2; n2++) {
            uint32_t baddr = sb + SM1_B
                + (uint32_t)(ks * 16 + ((l >> 3) & 1) * 8 + (l & 7)) * (BP * 2)
                + (uint32_t)(wn * 32 + n2 * 16 + (l >> 4) * 8) * 2;
            LDSM4T(bf[n2][0], bf[n2][1], bf[n2][2], bf[n2][3], baddr);
        }
#pragma unroll
        for (int ma = 0; ma < 4; ma++) {
            MMA16816(acc[ma][0], af[ma][0], af[ma][1], af[ma][2], af[ma][3], bf[0][0], bf[0][1]);
            MMA16816(acc[ma][1], af[ma][0], af[ma][1], af[ma][2], af[ma][3], bf[0][2], bf[0][3]);
            MMA16816(acc[ma][2], af[ma][0], af[ma][1], af[ma][2], af[ma][3], bf[1][0], bf[1][1]);
            MMA16816(acc[ma][3], af[ma][0], af[ma][1], af[ma][2], af[ma][3], bf[1][2], bf[1][3]);
        }
    }

#pragma unroll
    for (int nt = 0; nt < 4; nt++) {
        const int np = wn * 32 + nt * 8 + (l & 3) * 2;
        const int u = np >> 2, g = np & 3;
        const float b0 = __ldg(bias + (size_t)k * G_ + g * 256 + nb * 32 + u);
        const float b1 = __ldg(bias + (size_t)k * G_ + (g + 1) * 256 + nb * 32 + u);
#pragma unroll
        for (int ma = 0; ma < 4; ma++) {
            const int m0 = bm + wm * 64 + ma * 16 + (l >> 2);
            float* p0 = g_xw + ((size_t)m0 * K_ + k) * G_ + nb * 128 + np;
            float* p1 = g_xw + ((size_t)(m0 + 8) * K_ + k) * G_ + nb * 128 + np;
            *(float2*)p0 = make_float2(acc[ma][nt][0] + b0, acc[ma][nt][1] + b1);
            *(float2*)p1 = make_float2(acc[ma][nt][2] + b0, acc[ma][nt][3] + b1);
        }
    }

    // Publish completion with RELEASE semantics (gpu scope).
    __threadfence();
    __syncthreads();
    if (tid == 0)
        asm volatile("red.release.gpu.global.add.u32 [%0], %1;"
                     :: "l"(&g_flags[k][chunk]), "r"(1u) : "memory");
}

// ---------------------------------------------------------------------------
// Kernel 2: recurrence v6 + chunk-readiness spin. xw loads use __ldcg (L2,
// the coherence point) — __ldg's nc path can serve STALE prefetched lines
// when the producer kernel writes g_xw concurrently (R11's failure mode).
// ---------------------------------------------------------------------------
#define UTP   264
#define SLAB  2304
#define HALFB 1152
#define HBUF  (4 * SLAB)
#define TXH   (3u * HALFB)
#define OFF_H   0
#define OFF_STG (2 * HBUF)
#define OFF_MB  (OFF_STG + 2 * SLAB)
#define OFF_UT  (OFF_MB + 128)
#define SM2_TOT (OFF_UT + 256 * UTP * 2)

__global__ __launch_bounds__(512, 1) __cluster_dims__(4, 1, 1)
void lstm_rec_v6(const float* __restrict__ U, float* __restrict__ out)
{
    extern __shared__ char smem[];
    const uint32_t sb = smem_u32(smem);
    const int tid = threadIdx.x, w = tid >> 5, l = tid & 31;
    const int k = blockIdx.x >> 2;
    uint32_t rank;
    asm("mov.u32 %0, %%cluster_ctarank;" : "=r"(rank));

    {
        const int j = tid >> 1, hf = tid & 1;
        const int wq = j >> 4, rr = j & 15;
        const int uloc = 4 * wq + (rr & 3), g = rr >> 2;
        const float* up = U + (size_t)k * NI_ * G_ + g * 256 + (int)rank * 64 + uloc;
        half* uts = (half*)(smem + OFF_UT) + (size_t)j * UTP;
        for (int i = hf * 128; i < hf * 128 + 128; i++)
            uts[i] = __float2half_rn(up[(size_t)i * G_]);
    }
    for (int idx = tid; idx < HBUF / 4; idx += 512)
        ((uint32_t*)(smem + OFF_H))[idx] = 0u;
    if (tid == 0) {
#pragma unroll
        for (int b = 0; b < 4; b++)
            asm volatile("mbarrier.init.shared.b64 [%0], %1;"
                         :: "r"(sb + OFF_MB + b * 8), "r"(1u) : "memory");
        asm volatile("mbarrier.arrive.expect_tx.shared.b64 _, [%0], %1;"
                     :: "r"(sb + OFF_MB + 16), "r"(TXH) : "memory");
        asm volatile("mbarrier.arrive.expect_tx.shared.b64 _, [%0], %1;"
                     :: "r"(sb + OFF_MB + 24), "r"(TXH) : "memory");
    }
    __syncthreads();

    uint32_t Af[16][4];
    {
        const uint32_t abase = sb + OFF_UT
            + (uint32_t)(16 * w + (l & 15)) * (UTP * 2) + (uint32_t)(l >> 4) * 16;
#pragma unroll
        for (int ks = 0; ks < 16; ks++)
            LDSM4(Af[ks][0], Af[ks][1], Af[ks][2], Af[ks][3], abase + ks * 32);
    }

    asm volatile("barrier.cluster.arrive.aligned;" ::: "memory");
    asm volatile("barrier.cluster.wait.aligned;" ::: "memory");

    const bool lo16 = (l < 16);
    const int  uloc = 4 * w + ((l >> 2) & 3);
    const int  cell0 = 2 * (l & 3) + (lo16 ? 0 : 1);
    const int  colx = 4 * ((int)rank * 64 + uloc);
    const uint32_t aHalf = sb + OFF_H + (uint32_t)(l & 7) * 144 + (uint32_t)((l >> 3) & 1) * 16;
    const float* xw0p = g_xw + ((size_t)cell0 * T_ * K_ + k) * G_ + colx;
    const float* xw1p = g_xw + ((size_t)(cell0 + 8) * T_ * K_ + k) * G_ + colx;
    const bool sender = ((l >> 2) & 1) == 0;
    float c0 = 0.0f, c1 = 0.0f;
    int phA0 = 0, phA1 = 0, phB0 = 0, phB1 = 0;

    for (int t = 0; t < T_; t++) {
        const int p = t & 1;
        const uint32_t mbA = sb + OFF_MB + (uint32_t)p * 16;
        const uint32_t mbB = mbA + 8;

        // Wait for producer GEMM to finish this 128-step chunk (4 waits total).
        if ((t & 127) == 0) {
            const int ch = t >> 7;
            unsigned int v;
            do {
                asm volatile("ld.acquire.gpu.global.u32 %0, [%1];"
                             : "=r"(v) : "l"(&g_flags[k][ch]) : "memory");
                if (v < 128u) __nanosleep(1000);
            } while (v < 128u);
        }

        // xw loads MUST be .cg (L2-coherent) — nc/L1 may hold stale prefetches.
        float4 xwa = __ldcg((const float4*)(xw0p + (size_t)t * (K_ * G_)));
        float4 xwb = __ldcg((const float4*)(xw1p + (size_t)t * (K_ * G_)));

        // ================= PHASE A : cells 0-7 =================
        if (t > 0) {
            if (p) { MBAR_WAIT(mbA, (uint32_t)phA1); phA1 ^= 1; }
            else   { MBAR_WAIT(mbA, (uint32_t)phA0); phA0 ^= 1; }
        }
        if (tid == 0)
            asm volatile("mbarrier.arrive.expect_tx.shared.b64 _, [%0], %1;"
                         :: "r"(mbA), "r"(TXH) : "memory");

        float dP[4] = {0, 0, 0, 0}, dQ[4] = {0, 0, 0, 0};
        {
            const uint32_t hA = aHalf + (uint32_t)p * HBUF;
#pragma unroll
            for (int ks = 0; ks < 8; ks++) {
                uint32_t b0, b1;
                LDSM2(b0, b1, hA + (uint32_t)(ks >> 2) * SLAB + (uint32_t)(ks & 3) * 32);
                MMA16816(dP, Af[ks][0], Af[ks][1], Af[ks][2], Af[ks][3], b0, b1);
            }
#pragma unroll
            for (int ks = 8; ks < 16; ks++) {
                uint32_t b0, b1;
                LDSM2(b0, b1, hA + (uint32_t)(ks >> 2) * SLAB + (uint32_t)(ks & 3) * 32);
                MMA16816(dQ, Af[ks][0], Af[ks][1], Af[ks][2], Af[ks][3], b0, b1);
            }
        }
        float dLo[4];
#pragma unroll
        for (int e = 0; e < 4; e++) dLo[e] = dP[e] + dQ[e];

        float xa = __shfl_xor_sync(0xFFFFFFFFu, lo16 ? dLo[1] : dLo[0], 16);
        float xb = __shfl_xor_sync(0xFFFFFFFFu, lo16 ? dLo[3] : dLo[2], 16);
        float zA0, zA1, zA2, zA3;
        if (lo16) { zA0 = dLo[0]; zA1 = xa;     zA2 = dLo[2]; zA3 = xb;     }
        else      { zA0 = xa;     zA1 = dLo[1]; zA2 = xb;     zA3 = dLo[3]; }

        float av0 = tanhf(zA0 + xwa.x);
        float iv0 = hsig (zA1 + xwa.y);
        float fv0 = hsig (zA2 + xwa.z);
        float ov0 = hsig (zA3 + xwa.w);
        c0 = fmaf(fv0, c0, av0 * iv0);
        float h0 = ov0 * tanhf(c0);

        float q0 = __shfl_xor_sync(0xFFFFFFFFu, h0, 4);
        if (sender) {
            __half2 v = __floats2half2_rn(h0, q0);
            const uint32_t off = (uint32_t)cell0 * 144 + (uint32_t)uloc * 2;
            *(__half2*)(smem + OFF_STG + p * SLAB + off) = v;
            *(__half2*)(smem + OFF_H + (p ^ 1) * HBUF + rank * SLAB + off) = v;
        }
        out[(((size_t)cell0 * T_ + t) * K_ + k) * UN_ + (size_t)rank * 64 + uloc] = h0;

        __syncthreads();
        if (tid == 0) {
            asm volatile("fence.proxy.async;" ::: "memory");
            const uint32_t src  = sb + OFF_STG + (uint32_t)p * SLAB;
            const uint32_t dstL = sb + OFF_H + (uint32_t)(p ^ 1) * HBUF + rank * SLAB;
            const uint32_t mbL  = sb + OFF_MB + (uint32_t)(p ^ 1) * 16;
#pragma unroll
            for (int peer = 0; peer < 4; peer++) {
                if (peer == (int)rank) continue;
                uint32_t dstR, mbR;
                asm("mapa.shared::cluster.u32 %0, %1, %2;" : "=r"(dstR) : "r"(dstL), "r"(peer));
                asm("mapa.shared::cluster.u32 %0, %1, %2;" : "=r"(mbR)  : "r"(mbL),  "r"(peer));
                asm volatile(
                    "cp.async.bulk.shared::cluster.shared::cta.mbarrier::complete_tx::bytes "
                    "[%0], [%1], %2, [%3];"
                    :: "r"(dstR), "r"(src), "r"((uint32_t)HALFB), "r"(mbR) : "memory");
            }
        }

        // ================= PHASE B : cells 8-15 =================
        if (t > 0) {
            if (p) { MBAR_WAIT(mbB, (uint32_t)phB1); phB1 ^= 1; }
            else   { MBAR_WAIT(mbB, (uint32_t)phB0); phB0 ^= 1; }
        }
        if (tid == 0)
            asm volatile("mbarrier.arrive.expect_tx.shared.b64 _, [%0], %1;"
                         :: "r"(mbB), "r"(TXH) : "memory");

        float eP[4] = {0, 0, 0, 0}, eQ[4] = {0, 0, 0, 0};
        {
            const uint32_t hB = aHalf + (uint32_t)p * HBUF + 8u * 144u;
#pragma unroll
            for (int ks = 0; ks < 8; ks++) {
                uint32_t b0, b1;
                LDSM2(b0, b1, hB + (uint32_t)(ks >> 2) * SLAB + (uint32_t)(ks & 3) * 32);
                MMA16816(eP, Af[ks][0], Af[ks][1], Af[ks][2], Af[ks][3], b0, b1);
            }
#pragma unroll
            for (int ks = 8; ks < 16; ks++) {
                uint32_t b0, b1;
                LDSM2(b0, b1, hB + (uint32_t)(ks >> 2) * SLAB + (uint32_t)(ks & 3) * 32);
                MMA16816(eQ, Af[ks][0], Af[ks][1], Af[ks][2], Af[ks][3], b0, b1);
            }
        }
        float dHi[4];
#pragma unroll
        for (int e = 0; e < 4; e++) dHi[e] = eP[e] + eQ[e];

        float xc = __shfl_xor_sync(0xFFFFFFFFu, lo16 ? dHi[1] : dHi[0], 16);
        float xd = __shfl_xor_sync(0xFFFFFFFFu, lo16 ? dHi[3] : dHi[2], 16);
        float zB0, zB1, zB2, zB3;
        if (lo16) { zB0 = dHi[0]; zB1 = xc;     zB2 = dHi[2]; zB3 = xd;     }
        else      { zB0 = xc;     zB1 = dHi[1]; zB2 = xd;     zB3 = dHi[3]; }

        float av1 = tanhf(zB0 + xwb.x);
        float iv1 = hsig (zB1 + xwb.y);
        float fv1 = hsig (zB2 + xwb.z);
        float ov1 = hsig (zB3 + xwb.w);
        c1 = fmaf(fv1, c1, av1 * iv1);
        float h1 = ov1 * tanhf(c1);

        float q1 = __shfl_xor_sync(0xFFFFFFFFu, h1, 4);
        if (sender) {
            __half2 v = __floats2half2_rn(h1, q1);
            const uint32_t off = (uint32_t)(cell0 + 8) * 144 + (uint32_t)uloc * 2;
            *(__half2*)(smem + OFF_STG + p * SLAB + off) = v;
            *(__half2*)(smem + OFF_H + (p ^ 1) * HBUF + rank * SLAB + off) = v;
        }
        out[(((size_t)(cell0 + 8) * T_ + t) * K_ + k) * UN_ + (size_t)rank * 64 + uloc] = h1;

        __syncthreads();
        if (tid == 0) {
            asm volatile("fence.proxy.async;" ::: "memory");
            const uint32_t src  = sb + OFF_STG + (uint32_t)p * SLAB + HALFB;
            const uint32_t dstL = sb + OFF_H + (uint32_t)(p ^ 1) * HBUF + rank * SLAB + HALFB;
            const uint32_t mbL  = sb + OFF_MB + (uint32_t)(p ^ 1) * 16 + 8;
#pragma unroll
            for (int peer = 0; peer < 4; peer++) {
                if (peer == (int)rank) continue;
                uint32_t dstR, mbR;
                asm("mapa.shared::cluster.u32 %0, %1, %2;" : "=r"(dstR) : "r"(dstL), "r"(peer));
                asm("mapa.shared::cluster.u32 %0, %1, %2;" : "=r"(mbR)  : "r"(mbL),  "r"(peer));
                asm volatile(
                    "cp.async.bulk.shared::cluster.shared::cta.mbarrier::complete_tx::bytes "
                    "[%0], [%1], %2, [%3];"
                    :: "r"(dstR), "r"(src), "r"((uint32_t)HALFB), "r"(mbR) : "memory");
            }
        }
    }

    asm volatile("barrier.cluster.arrive.aligned;" ::: "memory");
    asm volatile("barrier.cluster.wait.aligned;" ::: "memory");
}

// ---------------------------------------------------------------------------
// Launch: fork GEMM and recurrence onto independent graph branches (overlap).
// ---------------------------------------------------------------------------
extern "C" void kernel_launch(void* const* d_in, const int* in_sizes, int n_in,
                              void* d_out, int out_size)
{
    const float* x = (const float*)d_in[0];
    const float* W = (const float*)d_in[1];
    const float* U = (const float*)d_in[2];
    const float* b = (const float*)d_in[3];
    float* out = (float*)d_out;

    static cudaStream_t s2 = nullptr;
    static cudaEvent_t evFork = nullptr, evJoin = nullptr;
    static void* flagsPtr = nullptr;
    if (!s2) {
        cudaStreamCreateWithFlags(&s2, cudaStreamNonBlocking);
        cudaEventCreateWithFlags(&evFork, cudaEventDisableTiming);
        cudaEventCreateWithFlags(&evJoin, cudaEventDisableTiming);
        cudaGetSymbolAddress(&flagsPtr, g_flags);
        cudaFuncSetAttribute(gemm_xw_hmma, cudaFuncAttributeMaxDynamicSharedMemorySize, SM1_TOT);
        cudaFuncSetAttribute(lstm_rec_v6, cudaFuncAttributeMaxDynamicSharedMemorySize, SM2_TOT);
    }

    // Reset progress flags (captured as a graph node; re-run on every replay).
    cudaMemsetAsync(flagsPtr, 0, sizeof(unsigned int) * K_ * 4, 0);

    // Fork: recurrence on s2, GEMM on the main stream — independent nodes.
    cudaEventRecord(evFork, 0);
    cudaStreamWaitEvent(s2, evFork, 0);

    lstm_rec_v6<<<K_ * 4, 512, SM2_TOT, s2>>>(U, out);

    dim3 g1(8, 128, 4);   // x=nb, y=k*16+cell, z=chunk (slowest -> first)
    gemm_xw_hmma<<<g1, 256, SM1_TOT, 0>>>(x, W, b);

    // Join.
    cudaEventRecord(evJoin, s2);
    cudaStreamWaitEvent(0, evJoin, 0);
}

// round 13
// speedup vs baseline: 1.3842x; 1.0627x over previous
#include <cuda_runtime.h>
#include <cuda_fp16.h>
#include <cstdint>

#define B_  16
#define T_  512
#define K_  8
#define NI_ 256
#define UN_ 256
#define G_  1024   // 4*UNITS

// Hoisted x@W + b, GATE-INTERLEAVED: col = 4*u + g  (u=unit 0..255, g=gate).
__device__ float g_xw[(size_t)B_ * T_ * K_ * G_];
// Progress flags: g_flags[k][chunk] counts completed GEMM blocks (target 128).
__device__ unsigned int g_flags[K_][8];

__device__ __forceinline__ uint32_t smem_u32(const void* p) {
    uint32_t a;
    asm("{ .reg .u64 t; cvta.to.shared.u64 t, %1; cvt.u32.u64 %0, t; }" : "=r"(a) : "l"(p));
    return a;
}
__device__ __forceinline__ float hsig(float v) {
    return fminf(fmaxf(fmaf(v, 0.2f, 0.5f), 0.0f), 1.0f);
}
// Branchless tanh: (e^2x - 1)/(e^2x + 1), clamped. ~2-3 ulp, no branches,
// 2 MUFU instead of tanhf's branchy ~20-instr path. On the h->h critical chain.
__device__ __forceinline__ float ftanh(float x) {
    float xc = fminf(fmaxf(x, -9.0f), 9.0f);
    float e = __expf(2.0f * xc);
    return __fdividef(e - 1.0f, e + 1.0f);
}

#define LDSM4(r0, r1, r2, r3, addr)                                              \
    asm volatile("ldmatrix.sync.aligned.m8n8.x4.shared.b16 {%0,%1,%2,%3}, [%4];" \
                 : "=r"(r0), "=r"(r1), "=r"(r2), "=r"(r3) : "r"(addr))
#define LDSM2(r0, r1, addr)                                                      \
    asm volatile("ldmatrix.sync.aligned.m8n8.x2.shared.b16 {%0,%1}, [%2];"       \
                 : "=r"(r0), "=r"(r1) : "r"(addr))
#define LDSM4T(r0, r1, r2, r3, addr)                                             \
    asm volatile("ldmatrix.sync.aligned.m8n8.x4.trans.shared.b16 {%0,%1,%2,%3}, [%4];" \
                 : "=r"(r0), "=r"(r1), "=r"(r2), "=r"(r3) : "r"(addr))
#define MMA16816(d, a0, a1, a2, a3, b0, b1)                                      \
    asm volatile("mma.sync.aligned.m16n8k16.row.col.f32.f16.f16.f32 "            \
                 "{%0,%1,%2,%3}, {%4,%5,%6,%7}, {%8,%9}, {%0,%1,%2,%3};"         \
                 : "+f"(d[0]), "+f"(d[1]), "+f"(d[2]), "+f"(d[3])                \
                 : "r"(a0), "r"(a1), "r"(a2), "r"(a3), "r"(b0), "r"(b1))

#define MBAR_WAIT(addr, ph) do {                                                          \
    uint32_t _done;                                                                       \
    asm volatile("{ .reg .pred p; mbarrier.try_wait.parity.acquire.cta.shared::cta.b64 "  \
                 "p, [%1], %2; selp.b32 %0,1,0,p; }"                                      \
                 : "=r"(_done) : "r"(addr), "r"(ph) : "memory");                          \
    while (!_done) {                                                                      \
        asm volatile("{ .reg .pred p; mbarrier.try_wait.parity.acquire.cta.shared::cta.b64 " \
                     "p, [%1], %2, 0x989680; selp.b32 %0,1,0,p; }"                        \
                     : "=r"(_done) : "r"(addr), "r"(ph) : "memory");                      \
    }                                                                                     \
} while (0)

// ---------------------------------------------------------------------------
// Kernel 1 (HMMA): x@W + b into g_xw, col = 4u+g. M-tile 64 (2 blocks/SM),
// 8 chunk-major t-chunks of 64 steps, release completion flags.
// ---------------------------------------------------------------------------
#define AP 264
#define BP 136
#define SM1_A 0
#define SM1_B (64 * AP * 2)                  // 33792
#define SM1_TOT (SM1_B + 256 * BP * 2)       // 103424 (~101 KB -> 2 blocks/SM)

__global__ __launch_bounds__(256, 2) void gemm_xw_hmma(
    const float* __restrict__ x, const float* __restrict__ W,
    const float* __restrict__ bias)
{
    extern __shared__ char smem[];
    const uint32_t sb = smem_u32(smem);
    const int tid = threadIdx.x, w = tid >> 5, l = tid & 31;
    const int nb    = blockIdx.x;            // 32-unit block
    const int k     = blockIdx.y >> 4;
    const int cell  = blockIdx.y & 15;
    const int chunk = blockIdx.z;            // 64-step t-chunk (scheduled first)
    const int bm    = (cell * 8 + chunk) * 64;

    half* As = (half*)(smem + SM1_A);
    for (int idx = tid; idx < 64 * 64; idx += 256) {
        int r = idx >> 6, c4 = idx & 63;
        float4 v = *(const float4*)(x + ((size_t)(bm + r) * K_ + k) * NI_ + c4 * 4);
        __half2 h01 = __floats2half2_rn(v.x, v.y);
        __half2 h23 = __floats2half2_rn(v.z, v.w);
        uint2 pk = make_uint2(*(uint32_t*)&h01, *(uint32_t*)&h23);
        *(uint2*)(As + r * AP + c4 * 4) = pk;
    }
    half* Bs = (half*)(smem + SM1_B);
    for (int idx = tid; idx < 256 * 128; idx += 256) {
        int i = idx >> 7, np = idx & 127;
        int u = np >> 2, g = np & 3;
        Bs[i * BP + np] = __float2half_rn(
            W[((size_t)k * NI_ + i) * G_ + g * 256 + nb * 32 + u]);
    }
    __syncthreads();

    const int wm = w >> 2, wn = w & 3;       // warp tile: 32m x 32n
    float acc[2][4][4];
#pragma unroll
    for (int a = 0; a < 2; a++)
#pragma unroll
        for (int b = 0; b < 4; b++)
#pragma unroll
            for (int e = 0; e < 4; e++) acc[a][b][e] = 0.0f;

#pragma unroll
    for (int ks = 0; ks < 16; ks++) {
        uint32_t af[2][4], bf[2][4];
#pragma unroll
        for (int ma = 0; ma < 2; ma++) {
            uint32_t aaddr = sb + SM1_A
                + (uint32_t)(wm * 32 + ma * 16 + (l & 15)) * (AP * 2)
                + (uint32_t)ks * 32 + (uint32_t)(l >> 4) * 16;
            LDSM4(af[ma][0], af[ma][1], af[ma][2], af[ma][3], aaddr);
        }
#pragma unroll
        for (int n2 = 0; n2 < 2; n2++) {
            uint32_t baddr = sb + SM1_B
                + (uint32_t)(ks * 16 + ((l >> 3) & 1) * 8 + (l & 7)) * (BP * 2)
                + (uint32_t)(wn * 32 + n2 * 16 + (l >> 4) * 8) * 2;
            LDSM4T(bf[n2][0], bf[n2][1], bf[n2][2], bf[n2][3], baddr);
        }
#pragma unroll
        for (int ma = 0; ma < 2; ma++) {
            MMA16816(acc[ma][0], af[ma][0], af[ma][1], af[ma][2], af[ma][3], bf[0][0], bf[0][1]);
            MMA16816(acc[ma][1], af[ma][0], af[ma][1], af[ma][2], af[ma][3], bf[0][2], bf[0][3]);
            MMA16816(acc[ma][2], af[ma][0], af[ma][1], af[ma][2], af[ma][3], bf[1][0], bf[1][1]);
            MMA16816(acc[ma][3], af[ma][0], af[ma][1], af[ma][2], af[ma][3], bf[1][2], bf[1][3]);
        }
    }

#pragma unroll
    for (int nt = 0; nt < 4; nt++) {
        const int np = wn * 32 + nt * 8 + (l & 3) * 2;
        const int u = np >> 2, g = np & 3;
        const float b0 = __ldg(bias + (size_t)k * G_ + g * 256 + nb * 32 + u);
        const float b1 = __ldg(bias + (size_t)k * G_ + (g + 1) * 256 + nb * 32 + u);
#pragma unroll
        for (int ma = 0; ma < 2; ma++) {
            const int m0 = bm + wm * 32 + ma * 16 + (l >> 2);
            float* p0 = g_xw + ((size_t)m0 * K_ + k) * G_ + nb * 128 + np;
            float* p1 = g_xw + ((size_t)(m0 + 8) * K_ + k) * G_ + nb * 128 + np;
            *(float2*)p0 = make_float2(acc[ma][nt][0] + b0, acc[ma][nt][1] + b1);
            *(float2*)p1 = make_float2(acc[ma][nt][2] + b0, acc[ma][nt][3] + b1);
        }
    }

    // Publish completion with RELEASE semantics (gpu scope).
    __threadfence();
    __syncthreads();
    if (tid == 0)
        asm volatile("red.release.gpu.global.add.u32 [%0], %1;"
                     :: "l"(&g_flags[k][chunk]), "r"(1u) : "memory");
}

// ---------------------------------------------------------------------------
// Kernel 2: recurrence v6 + 64-step chunk spin; xw via __ldcg (coherent);
// ftanh on the critical chain.
// ---------------------------------------------------------------------------
#define UTP   264
#define SLAB  2304
#define HALFB 1152
#define HBUF  (4 * SLAB)
#define TXH   (3u * HALFB)
#define OFF_H   0
#define OFF_STG (2 * HBUF)
#define OFF_MB  (OFF_STG + 2 * SLAB)
#define OFF_UT  (OFF_MB + 128)
#define SM2_TOT (OFF_UT + 256 * UTP * 2)

__global__ __launch_bounds__(512, 1) __cluster_dims__(4, 1, 1)
void lstm_rec_v6(const float* __restrict__ U, float* __restrict__ out)
{
    extern __shared__ char smem[];
    const uint32_t sb = smem_u32(smem);
    const int tid = threadIdx.x, w = tid >> 5, l = tid & 31;
    const int k = blockIdx.x >> 2;
    uint32_t rank;
    asm("mov.u32 %0, %%cluster_ctarank;" : "=r"(rank));

    {
        const int j = tid >> 1, hf = tid & 1;
        const int wq = j >> 4, rr = j & 15;
        const int uloc = 4 * wq + (rr & 3), g = rr >> 2;
        const float* up = U + (size_t)k * NI_ * G_ + g * 256 + (int)rank * 64 + uloc;
        half* uts = (half*)(smem + OFF_UT) + (size_t)j * UTP;
        for (int i = hf * 128; i < hf * 128 + 128; i++)
            uts[i] = __float2half_rn(up[(size_t)i * G_]);
    }
    for (int idx = tid; idx < HBUF / 4; idx += 512)
        ((uint32_t*)(smem + OFF_H))[idx] = 0u;
    if (tid == 0) {
#pragma unroll
        for (int b = 0; b < 4; b++)
            asm volatile("mbarrier.init.shared.b64 [%0], %1;"
                         :: "r"(sb + OFF_MB + b * 8), "r"(1u) : "memory");
        asm volatile("mbarrier.arrive.expect_tx.shared.b64 _, [%0], %1;"
                     :: "r"(sb + OFF_MB + 16), "r"(TXH) : "memory");
        asm volatile("mbarrier.arrive.expect_tx.shared.b64 _, [%0], %1;"
                     :: "r"(sb + OFF_MB + 24), "r"(TXH) : "memory");
    }
    __syncthreads();

    uint32_t Af[16][4];
    {
        const uint32_t abase = sb + OFF_UT
            + (uint32_t)(16 * w + (l & 15)) * (UTP * 2) + (uint32_t)(l >> 4) * 16;
#pragma unroll
        for (int ks = 0; ks < 16; ks++)
            LDSM4(Af[ks][0], Af[ks][1], Af[ks][2], Af[ks][3], abase + ks * 32);
    }

    asm volatile("barrier.cluster.arrive.aligned;" ::: "memory");
    asm volatile("barrier.cluster.wait.aligned;" ::: "memory");

    const bool lo16 = (l < 16);
    const int  uloc = 4 * w + ((l >> 2) & 3);
    const int  cell0 = 2 * (l & 3) + (lo16 ? 0 : 1);
    const int  colx = 4 * ((int)rank * 64 + uloc);
    const uint32_t aHalf = sb + OFF_H + (uint32_t)(l & 7) * 144 + (uint32_t)((l >> 3) & 1) * 16;
    const float* xw0p = g_xw + ((size_t)cell0 * T_ * K_ + k) * G_ + colx;
    const float* xw1p = g_xw + ((size_t)(cell0 + 8) * T_ * K_ + k) * G_ + colx;
    const bool sender = ((l >> 2) & 1) == 0;
    float c0 = 0.0f, c1 = 0.0f;
    int phA0 = 0, phA1 = 0, phB0 = 0, phB1 = 0;

    for (int t = 0; t < T_; t++) {
        const int p = t & 1;
        const uint32_t mbA = sb + OFF_MB + (uint32_t)p * 16;
        const uint32_t mbB = mbA + 8;

        // Wait for producer GEMM to finish this 64-step chunk (8 waits total).
        if ((t & 63) == 0) {
            const int ch = t >> 6;
            unsigned int v;
            do {
                asm volatile("ld.acquire.gpu.global.u32 %0, [%1];"
                             : "=r"(v) : "l"(&g_flags[k][ch]) : "memory");
                if (v < 128u) __nanosleep(1000);
            } while (v < 128u);
        }

        // xw loads MUST be .cg (L2-coherent) — nc/L1 may hold stale prefetches.
        float4 xwa = __ldcg((const float4*)(xw0p + (size_t)t * (K_ * G_)));
        float4 xwb = __ldcg((const float4*)(xw1p + (size_t)t * (K_ * G_)));

        // ================= PHASE A : cells 0-7 =================
        if (t > 0) {
            if (p) { MBAR_WAIT(mbA, (uint32_t)phA1); phA1 ^= 1; }
            else   { MBAR_WAIT(mbA, (uint32_t)phA0); phA0 ^= 1; }
        }
        if (tid == 0)
            asm volatile("mbarrier.arrive.expect_tx.shared.b64 _, [%0], %1;"
                         :: "r"(mbA), "r"(TXH) : "memory");

        float dP[4] = {0, 0, 0, 0}, dQ[4] = {0, 0, 0, 0};
        {
            const uint32_t hA = aHalf + (uint32_t)p * HBUF;
#pragma unroll
            for (int ks = 0; ks < 8; ks++) {
                uint32_t b0, b1;
                LDSM2(b0, b1, hA + (uint32_t)(ks >> 2) * SLAB + (uint32_t)(ks & 3) * 32);
                MMA16816(dP, Af[ks][0], Af[ks][1], Af[ks][2], Af[ks][3], b0, b1);
            }
#pragma unroll
            for (int ks = 8; ks < 16; ks++) {
                uint32_t b0, b1;
                LDSM2(b0, b1, hA + (uint32_t)(ks >> 2) * SLAB + (uint32_t)(ks & 3) * 32);
                MMA16816(dQ, Af[ks][0], Af[ks][1], Af[ks][2], Af[ks][3], b0, b1);
            }
        }
        float dLo[4];
#pragma unroll
        for (int e = 0; e < 4; e++) dLo[e] = dP[e] + dQ[e];

        float xa = __shfl_xor_sync(0xFFFFFFFFu, lo16 ? dLo[1] : dLo[0], 16);
        float xb = __shfl_xor_sync(0xFFFFFFFFu, lo16 ? dLo[3] : dLo[2], 16);
        float zA0, zA1, zA2, zA3;
        if (lo16) { zA0 = dLo[0]; zA1 = xa;     zA2 = dLo[2]; zA3 = xb;     }
        else      { zA0 = xa;     zA1 = dLo[1]; zA2 = xb;     zA3 = dLo[3]; }

        float av0 = ftanh(zA0 + xwa.x);
        float iv0 = hsig (zA1 + xwa.y);
        float fv0 = hsig (zA2 + xwa.z);
        float ov0 = hsig (zA3 + xwa.w);
        c0 = fmaf(fv0, c0, av0 * iv0);
        float h0 = ov0 * ftanh(c0);

        float q0 = __shfl_xor_sync(0xFFFFFFFFu, h0, 4);
        if (sender) {
            __half2 v = __floats2half2_rn(h0, q0);
            const uint32_t off = (uint32_t)cell0 * 144 + (uint32_t)uloc * 2;
            *(__half2*)(smem + OFF_STG + p * SLAB + off) = v;
            *(__half2*)(smem + OFF_H + (p ^ 1) * HBUF + rank * SLAB + off) = v;
        }
        out[(((size_t)cell0 * T_ + t) * K_ + k) * UN_ + (size_t)rank * 64 + uloc] = h0;

        __syncthreads();
        if (tid == 0) {
            asm volatile("fence.proxy.async;" ::: "memory");
            const uint32_t src  = sb + OFF_STG + (uint32_t)p * SLAB;
            const uint32_t dstL = sb + OFF_H + (uint32_t)(p ^ 1) * HBUF + rank * SLAB;
            const uint32_t mbL  = sb + OFF_MB + (uint32_t)(p ^ 1) * 16;
#pragma unroll
            for (int peer = 0; peer < 4; peer++) {
                if (peer == (int)rank) continue;
                uint32_t dstR, mbR;
                asm("mapa.shared::cluster.u32 %0, %1, %2;" : "=r"(dstR) : "r"(dstL), "r"(peer));
                asm("mapa.shared::cluster.u32 %0, %1, %2;" : "=r"(mbR)  : "r"(mbL),  "r"(peer));
                asm volatile(
                    "cp.async.bulk.shared::cluster.shared::cta.mbarrier::complete_tx::bytes "
                    "[%0], [%1], %2, [%3];"
                    :: "r"(dstR), "r"(src), "r"((uint32_t)HALFB), "r"(mbR) : "memory");
            }
        }

        // ================= PHASE B : cells 8-15 =================
        if (t > 0) {
            if (p) { MBAR_WAIT(mbB, (uint32_t)phB1); phB1 ^= 1; }
            else   { MBAR_WAIT(mbB, (uint32_t)phB0); phB0 ^= 1; }
        }
        if (tid == 0)
            asm volatile("mbarrier.arrive.expect_tx.shared.b64 _, [%0], %1;"
                         :: "r"(mbB), "r"(TXH) : "memory");

        float eP[4] = {0, 0, 0, 0}, eQ[4] = {0, 0, 0, 0};
        {
            const uint32_t hB = aHalf + (uint32_t)p * HBUF + 8u * 144u;
#pragma unroll
            for (int ks = 0; ks < 8; ks++) {
                uint32_t b0, b1;
                LDSM2(b0, b1, hB + (uint32_t)(ks >> 2) * SLAB + (uint32_t)(ks & 3) * 32);
                MMA16816(eP, Af[ks][0], Af[ks][1], Af[ks][2], Af[ks][3], b0, b1);
            }
#pragma unroll
            for (int ks = 8; ks < 16; ks++) {
                uint32_t b0, b1;
                LDSM2(b0, b1, hB + (uint32_t)(ks >> 2) * SLAB + (uint32_t)(ks & 3) * 32);
                MMA16816(eQ, Af[ks][0], Af[ks][1], Af[ks][2], Af[ks][3], b0, b1);
            }
        }
        float dHi[4];
#pragma unroll
        for (int e = 0; e < 4; e++) dHi[e] = eP[e] + eQ[e];

        float xc = __shfl_xor_sync(0xFFFFFFFFu, lo16 ? dHi[1] : dHi[0], 16);
        float xd = __shfl_xor_sync(0xFFFFFFFFu, lo16 ? dHi[3] : dHi[2], 16);
        float zB0, zB1, zB2, zB3;
        if (lo16) { zB0 = dHi[0]; zB1 = xc;     zB2 = dHi[2]; zB3 = xd;     }
        else      { zB0 = xc;     zB1 = dHi[1]; zB2 = xd;     zB3 = dHi[3]; }

        float av1 = ftanh(zB0 + xwb.x);
        float iv1 = hsig (zB1 + xwb.y);
        float fv1 = hsig (zB2 + xwb.z);
        float ov1 = hsig (zB3 + xwb.w);
        c1 = fmaf(fv1, c1, av1 * iv1);
        float h1 = ov1 * ftanh(c1);

        float q1 = __shfl_xor_sync(0xFFFFFFFFu, h1, 4);
        if (sender) {
            __half2 v = __floats2half2_rn(h1, q1);
            const uint32_t off = (uint32_t)(cell0 + 8) * 144 + (uint32_t)uloc * 2;
            *(__half2*)(smem + OFF_STG + p * SLAB + off) = v;
            *(__half2*)(smem + OFF_H + (p ^ 1) * HBUF + rank * SLAB + off) = v;
        }
        out[(((size_t)(cell0 + 8) * T_ + t) * K_ + k) * UN_ + (size_t)rank * 64 + uloc] = h1;

        __syncthreads();
        if (tid == 0) {
            asm volatile("fence.proxy.async;" ::: "memory");
            const uint32_t src  = sb + OFF_STG + (uint32_t)p * SLAB + HALFB;
            const uint32_t dstL = sb + OFF_H + (uint32_t)(p ^ 1) * HBUF + rank * SLAB + HALFB;
            const uint32_t mbL  = sb + OFF_MB + (uint32_t)(p ^ 1) * 16 + 8;
#pragma unroll
            for (int peer = 0; peer < 4; peer++) {
                if (peer == (int)rank) continue;
                uint32_t dstR, mbR;
                asm("mapa.shared::cluster.u32 %0, %1, %2;" : "=r"(dstR) : "r"(dstL), "r"(peer));
                asm("mapa.shared::cluster.u32 %0, %1, %2;" : "=r"(mbR)  : "r"(mbL),  "r"(peer));
                asm volatile(
                    "cp.async.bulk.shared::cluster.shared::cta.mbarrier::complete_tx::bytes "
                    "[%0], [%1], %2, [%3];"
                    :: "r"(dstR), "r"(src), "r"((uint32_t)HALFB), "r"(mbR) : "memory");
            }
        }
    }

    asm volatile("barrier.cluster.arrive.aligned;" ::: "memory");
    asm volatile("barrier.cluster.wait.aligned;" ::: "memory");
}

// ---------------------------------------------------------------------------
// Launch: fork GEMM and recurrence onto independent graph branches (overlap).
// ---------------------------------------------------------------------------
extern "C" void kernel_launch(void* const* d_in, const int* in_sizes, int n_in,
                              void* d_out, int out_size)
{
    const float* x = (const float*)d_in[0];
    const float* W = (const float*)d_in[1];
    const float* U = (const float*)d_in[2];
    const float* b = (const float*)d_in[3];
    float* out = (float*)d_out;

    static cudaStream_t s2 = nullptr;
    static cudaEvent_t evFork = nullptr, evJoin = nullptr;
    static void* flagsPtr = nullptr;
    if (!s2) {
        cudaStreamCreateWithFlags(&s2, cudaStreamNonBlocking);
        cudaEventCreateWithFlags(&evFork, cudaEventDisableTiming);
        cudaEventCreateWithFlags(&evJoin, cudaEventDisableTiming);
        cudaGetSymbolAddress(&flagsPtr, g_flags);
        cudaFuncSetAttribute(gemm_xw_hmma, cudaFuncAttributeMaxDynamicSharedMemorySize, SM1_TOT);
        cudaFuncSetAttribute(lstm_rec_v6, cudaFuncAttributeMaxDynamicSharedMemorySize, SM2_TOT);
    }

    // Reset progress flags (captured as a graph node; re-run on every replay).
    cudaMemsetAsync(flagsPtr, 0, sizeof(unsigned int) * K_ * 8, 0);

    // Fork: recurrence on s2, GEMM on the main stream — independent nodes.
    cudaEventRecord(evFork, 0);
    cudaStreamWaitEvent(s2, evFork, 0);

    lstm_rec_v6<<<K_ * 4, 512, SM2_TOT, s2>>>(U, out);

    dim3 g1(8, 128, 8);   // x=nb, y=k*16+cell, z=chunk (slowest -> first)
    gemm_xw_hmma<<<g1, 256, SM1_TOT, 0>>>(x, W, b);

    // Join.
    cudaEventRecord(evJoin, s2);
    cudaStreamWaitEvent(0, evJoin, 0);
}